// round 5
// baseline (speedup 1.0000x reference)
#include <cuda_runtime.h>
#include <cuda_fp16.h>
#include <stdint.h>

#define B_SZ     4096
#define D0       1024
#define D1       8192
#define D2       8192
#define D3       10240
#define NNEUR    (D1 + D2 + D3)     // 26624
#define KCLS     10
#define GRP      (D3 / KCLS)        // 1024
#define TAU      30.0f
#define ROWS     4
#define R2       (ROWS / 2)
#define NTHREADS 1024
#define NWARP    (NTHREADS / 32)    // 32
#define CELLS    256                // 16 a-bank-pairs x 16 b-bank-pairs

// -------- final (permuted) per-neuron metadata --------
__device__ uint32_t g_idx[NNEUR];    // ia | (ib<<16)  (position-space indices)
__device__ uint2    g_coef[NNEUR];   // {half2(c0,c1), half2(c2,c3)}

// -------- staging (unpermuted) + permutations --------
__device__ uint32_t s_idx[NNEUR];
__device__ uint32_t s_c01[NNEUR];
__device__ uint32_t s_c23[NNEUR];
__device__ uint16_t d_perm1[D1], d_inv1[D1];
__device__ uint16_t d_perm2[D2], d_inv2[D2];
__device__ uint16_t d_perm3[D3];    // per-group (local) permutation

__constant__ float OPC[16][4] = {
    {0.f, 0.f, 0.f, 0.f}, {0.f, 0.f, 0.f, 1.f}, {0.f, 1.f, 0.f, -1.f}, {0.f, 1.f, 0.f, 0.f},
    {0.f, 0.f, 1.f, -1.f}, {0.f, 0.f, 1.f, 0.f}, {0.f, 1.f, 1.f, -2.f}, {0.f, 1.f, 1.f, -1.f},
    {1.f, -1.f, -1.f, 1.f}, {1.f, -1.f, -1.f, 2.f}, {1.f, 0.f, -1.f, 0.f}, {1.f, 0.f, -1.f, 1.f},
    {1.f, -1.f, 0.f, 0.f}, {1.f, -1.f, 0.f, 1.f}, {1.f, 0.f, 0.f, -1.f}, {1.f, 0.f, 0.f, 0.f}};

__global__ void precompute_kernel(
    const float* __restrict__ w1, const float* __restrict__ w2, const float* __restrict__ w3,
    const int* __restrict__ ia1, const int* __restrict__ ib1,
    const int* __restrict__ ia2, const int* __restrict__ ib2,
    const int* __restrict__ ia3, const int* __restrict__ ib3)
{
    int j = blockIdx.x * blockDim.x + threadIdx.x;
    if (j >= NNEUR) return;
    const float* w; int ia, ib;
    if (j < D1)            { w = w1 + (size_t)j * 16;               ia = ia1[j];            ib = ib1[j]; }
    else if (j < D1 + D2)  { int k = j - D1;      w = w2 + (size_t)k * 16; ia = ia2[k]; ib = ib2[k]; }
    else                   { int k = j - D1 - D2; w = w3 + (size_t)k * 16; ia = ia3[k]; ib = ib3[k]; }

    float v[16]; float m = -3.4e38f;
#pragma unroll
    for (int i = 0; i < 16; i++) { v[i] = w[i]; m = fmaxf(m, v[i]); }
    float s = 0.f;
#pragma unroll
    for (int i = 0; i < 16; i++) { v[i] = expf(v[i] - m); s += v[i]; }
    float inv = 1.f / s;
    float c0 = 0.f, c1 = 0.f, c2 = 0.f, c3 = 0.f;
#pragma unroll
    for (int i = 0; i < 16; i++) {
        float p = v[i] * inv;
        c0 = fmaf(p, OPC[i][0], c0);
        c1 = fmaf(p, OPC[i][1], c1);
        c2 = fmaf(p, OPC[i][2], c2);
        c3 = fmaf(p, OPC[i][3], c3);
    }
    s_idx[j] = (uint32_t)ia | ((uint32_t)ib << 16);
    __half2 h01 = __floats2half2_rn(c0, c1);
    __half2 h23 = __floats2half2_rn(c2, c3);
    s_c01[j] = *reinterpret_cast<uint32_t*>(&h01);
    s_c23[j] = *reinterpret_cast<uint32_t*>(&h23);
}

// ---- bank-dealing permutation builder (fast two-level scan) ---------------
// One CTA per group of D items. Deterministic: counts via __match_any,
// offsets via two-level in-smem scans. No atomics.
template<int D>
__global__ void __launch_bounds__(1024, 1)
build_perm_kernel(int metaBase, const uint16_t* __restrict__ remap,
                  uint16_t* __restrict__ perm, uint16_t* __restrict__ inv)
{
    constexpr int ITEMS  = D / 1024;
    constexpr int VW     = D / 32;        // virtual warps
    constexpr int CAP    = D / CELLS;     // slots per cell
    constexpr int SCNSTR = VW + 8;        // padded stride (bank-conflict-free scan)
    constexpr int CHUNKV = VW / 4;        // v-entries per scan chunk

    extern __shared__ __align__(16) uint16_t sm[];
    uint16_t* off    = sm;                         // [CELLS][SCNSTR] counts -> chunk-exclusive
    uint16_t* chbase = off + CELLS * SCNSTR;       // [CELLS][4] chunk bases
    uint16_t* csize  = chbase + CELLS * 4;         // CELLS
    uint16_t* exoff  = csize + CELLS;              // CELLS (inclusive scan of excess)
    uint16_t* ufoff  = exoff + CELLS;              // CELLS (inclusive scan of unfilled)
    uint16_t* ufp    = ufoff + CELLS;              // up to D unfilled positions

    const int tid  = threadIdx.x;
    const int lane = tid & 31;
    const int w    = tid >> 5;
    const uint32_t ltm = (1u << lane) - 1u;
    const int grpMeta = metaBase + blockIdx.x * D;

    {   // zero the count table (uint4-vectorized; CELLS*SCNSTR is a multiple of 8)
        uint4* z = reinterpret_cast<uint4*>(off);
        const int total = CELLS * SCNSTR / 8;
        uint4 zz = make_uint4(0, 0, 0, 0);
        for (int i = tid; i < total; i += 1024) z[i] = zz;
    }
    __syncthreads();

    int mycell[ITEMS], mylr[ITEMS];
#pragma unroll
    for (int k = 0; k < ITEMS; k++) {
        int j = k * 1024 + tid;
        uint32_t pk = s_idx[grpMeta + j];
        uint32_t a = pk & 0xffffu, b = pk >> 16;
        if (remap) { a = remap[a]; b = remap[b]; }
        int cell = (int)((a & 15u) * 16u + (b & 15u));
        uint32_t mask = __match_any_sync(0xffffffffu, cell);
        mycell[k] = cell;
        mylr[k]   = __popc(mask & ltm);
        if ((mask & ltm) == 0)                         // leader for this cell
            off[cell * SCNSTR + (k * 32 + w)] = (uint16_t)__popc(mask);
    }
    __syncthreads();

    // phase 1: per-(cell,chunk) exclusive scan, all 1024 threads
    {
        int c  = tid >> 2;
        int ch = tid & 3;
        uint16_t run = 0;
        int base = c * SCNSTR + ch * CHUNKV;
#pragma unroll 4
        for (int i = 0; i < CHUNKV; i++) {
            uint16_t t = off[base + i];
            off[base + i] = run;
            run = (uint16_t)(run + t);
        }
        chbase[c * 4 + ch] = run;                      // chunk totals (temp)
    }
    __syncthreads();

    // phase 2: per-cell combine chunk totals -> exclusive chunk bases + sizes
    if (tid < CELLS) {
        int c = tid;
        uint16_t b = 0;
#pragma unroll
        for (int ch = 0; ch < 4; ch++) {
            uint16_t t = chbase[c * 4 + ch];
            chbase[c * 4 + ch] = b;
            b = (uint16_t)(b + t);
        }
        csize[c] = b;
        exoff[c] = (b > CAP) ? (uint16_t)(b - CAP) : 0;
        ufoff[c] = (b < CAP) ? (uint16_t)(CAP - b) : 0;
    }
    __syncthreads();

    // Hillis-Steele inclusive scans over cells
    for (int d = 1; d < CELLS; d <<= 1) {
        uint16_t ve = 0, vu = 0;
        if (tid < CELLS && tid >= d) { ve = exoff[tid - d]; vu = ufoff[tid - d]; }
        __syncthreads();
        if (tid < CELLS && tid >= d) { exoff[tid] = (uint16_t)(exoff[tid] + ve); ufoff[tid] = (uint16_t)(ufoff[tid] + vu); }
        __syncthreads();
    }

    // emit unfilled positions, grouped by cell (deterministic order)
    if (tid < CELLS) {
        int c = tid, t = c >> 4, s = c & 15;
        int sz  = csize[c];
        int ufc = (sz < CAP) ? CAP - sz : 0;
        int base = ufoff[c] - ufc;                     // exclusive offset
        for (int m = sz; m < CAP; m++) {
            int p = (((s - t) & 15) + 16 * m) * 16 + t;
            ufp[base + (m - sz)] = (uint16_t)p;
        }
    }
    __syncthreads();

    // assign positions
#pragma unroll
    for (int k = 0; k < ITEMS; k++) {
        int j = k * 1024 + tid;
        int cell = mycell[k];
        int v = k * 32 + w;
        int grank = off[cell * SCNSTR + v] + chbase[cell * 4 + v / CHUNKV] + mylr[k];
        int t = cell >> 4, s = cell & 15;
        int p;
        if (grank < CAP) {
            p = (((s - t) & 15) + 16 * grank) * 16 + t;
        } else {
            int exc    = csize[cell] - CAP;            // > 0 here
            int exbase = exoff[cell] - exc;            // exclusive offset
            p = ufp[exbase + (grank - CAP)];
        }
        perm[blockIdx.x * D + p] = (uint16_t)j;
        if (inv) inv[blockIdx.x * D + j] = (uint16_t)p;
    }
}

// ---- merge: build permuted, index-remapped metadata ----------------------
__global__ void merge_meta_kernel()
{
    int j = blockIdx.x * blockDim.x + threadIdx.x;
    if (j >= NNEUR) return;
    if (j < D1) {
        int o = d_perm1[j];
        g_idx[j]  = s_idx[o];                // refs into xs: unpermuted
        g_coef[j] = make_uint2(s_c01[o], s_c23[o]);
    } else if (j < D1 + D2) {
        int o = D1 + d_perm2[j - D1];
        uint32_t pk = s_idx[o];
        uint32_t a = d_inv1[pk & 0xffffu], b = d_inv1[pk >> 16];
        g_idx[j]  = a | (b << 16);
        g_coef[j] = make_uint2(s_c01[o], s_c23[o]);
    } else {
        int p = j - D1 - D2;
        int g = p >> 10;
        int o = D1 + D2 + (g << 10) + d_perm3[(g << 10) + (p & 1023)];
        uint32_t pk = s_idx[o];
        uint32_t a = d_inv2[pk & 0xffffu], b = d_inv2[pk >> 16];
        g_idx[j]  = a | (b << 16);
        g_coef[j] = make_uint2(s_c01[o], s_c23[o]);
    }
}

// -------- main kernel: whole network resident in shared memory --------------

struct NeuronIn {
    uint32_t pk, u01, u23;
    uint2 a, b;
};

__device__ __forceinline__ void fetch_neuron(const uint2* __restrict__ src,
                                             int mj, NeuronIn& n)
{
    n.pk  = __ldg(&g_idx[mj]);
    uint2 cc = __ldg(&g_coef[mj]);
    n.u01 = cc.x;
    n.u23 = cc.y;
    n.a = src[n.pk & 0xffffu];
    n.b = src[n.pk >> 16];
}

__device__ __forceinline__ uint2 neuron_math(const NeuronIn& n)
{
    float2 c01 = __half22float2(*reinterpret_cast<const __half2*>(&n.u01));
    float2 c23 = __half22float2(*reinterpret_cast<const __half2*>(&n.u23));
    uint2 o;
#pragma unroll
    for (int r = 0; r < R2; r++) {
        uint32_t ua = (r == 0) ? n.a.x : n.a.y;
        uint32_t ub = (r == 0) ? n.b.x : n.b.y;
        float2 a = __half22float2(*reinterpret_cast<const __half2*>(&ua));
        float2 b = __half22float2(*reinterpret_cast<const __half2*>(&ub));
        float o0 = fmaf(fmaf(c23.y, b.x, c01.y), a.x, fmaf(c23.x, b.x, c01.x));
        float o1 = fmaf(fmaf(c23.y, b.y, c01.y), a.y, fmaf(c23.x, b.y, c01.x));
        __half2 h = __floats2half2_rn(o0, o1);
        uint32_t uh = *reinterpret_cast<uint32_t*>(&h);
        if (r == 0) o.x = uh; else o.y = uh;
    }
    return o;
}

__device__ __forceinline__ void run_layer(const uint2* __restrict__ src,
                                          uint2* __restrict__ dst,
                                          int metaBase, int D, int tid)
{
    const int iters = D / NTHREADS;
    NeuronIn cur, nxt;
    int j = tid;
    fetch_neuron(src, metaBase + j, cur);
#pragma unroll 2
    for (int it = 0; it < iters - 1; it++) {
        fetch_neuron(src, metaBase + j + NTHREADS, nxt);
        dst[j] = neuron_math(cur);
        cur = nxt;
        j += NTHREADS;
    }
    dst[j] = neuron_math(cur);
}

__global__ void __launch_bounds__(NTHREADS, 1)
diff_logic_main(const float* __restrict__ x, float* __restrict__ out)
{
    extern __shared__ __align__(16) uint32_t smem_raw[];
    uint2* xs = reinterpret_cast<uint2*>(smem_raw);
    uint2* h1 = xs + D0;
    uint2* h2 = h1 + D1;
    float* wacc = reinterpret_cast<float*>(h2 + D2);

    const int tid  = threadIdx.x;
    const int row0 = blockIdx.x * ROWS;

    {
        int col = tid;                                // D0 == NTHREADS == 1024
        float v0 = x[(size_t)(row0 + 0) * D0 + col];
        float v1 = x[(size_t)(row0 + 1) * D0 + col];
        float v2 = x[(size_t)(row0 + 2) * D0 + col];
        float v3 = x[(size_t)(row0 + 3) * D0 + col];
        __half2 p0 = __floats2half2_rn(v0, v1);
        __half2 p1 = __floats2half2_rn(v2, v3);
        uint2 slot;
        slot.x = *reinterpret_cast<uint32_t*>(&p0);
        slot.y = *reinterpret_cast<uint32_t*>(&p1);
        xs[col] = slot;
    }
    __syncthreads();

    run_layer(xs, h1, 0, D1, tid);
    __syncthreads();
    run_layer(h1, h2, D1, D2, tid);
    __syncthreads();

    const int lane = tid & 31;
    const int warp = tid >> 5;

    for (int g = 0; g < KCLS; g++) {
        float acc[ROWS];
#pragma unroll
        for (int r = 0; r < ROWS; r++) acc[r] = 0.f;
        {
            int mj = D1 + D2 + g * GRP + tid;
            NeuronIn n;
            fetch_neuron(h2, mj, n);
            float2 c01 = __half22float2(*reinterpret_cast<const __half2*>(&n.u01));
            float2 c23 = __half22float2(*reinterpret_cast<const __half2*>(&n.u23));
#pragma unroll
            for (int r = 0; r < R2; r++) {
                uint32_t ua = (r == 0) ? n.a.x : n.a.y;
                uint32_t ub = (r == 0) ? n.b.x : n.b.y;
                float2 a = __half22float2(*reinterpret_cast<const __half2*>(&ua));
                float2 b = __half22float2(*reinterpret_cast<const __half2*>(&ub));
                acc[2 * r + 0] += fmaf(fmaf(c23.y, b.x, c01.y), a.x, fmaf(c23.x, b.x, c01.x));
                acc[2 * r + 1] += fmaf(fmaf(c23.y, b.y, c01.y), a.y, fmaf(c23.x, b.y, c01.x));
            }
        }
#pragma unroll
        for (int r = 0; r < ROWS; r++) {
#pragma unroll
            for (int off = 16; off > 0; off >>= 1)
                acc[r] += __shfl_down_sync(0xffffffffu, acc[r], off);
        }
        if (lane == 0) {
#pragma unroll
            for (int r = 0; r < ROWS; r++)
                wacc[(g * NWARP + warp) * ROWS + r] = acc[r];
        }
    }
    __syncthreads();

    if (tid < KCLS * ROWS) {
        int g = tid / ROWS;
        int r = tid - g * ROWS;
        float s = 0.f;
#pragma unroll
        for (int w = 0; w < NWARP; w++)
            s += wacc[(g * NWARP + w) * ROWS + r];
        out[(size_t)(row0 + r) * KCLS + g] = s * (1.f / TAU);
    }
}

// -----------------------------------------------------------------------------

extern "C" void kernel_launch(void* const* d_in, const int* in_sizes, int n_in,
                              void* d_out, int out_size)
{
    (void)in_sizes; (void)n_in; (void)out_size;
    const float* x  = (const float*)d_in[0];
    const float* w1 = (const float*)d_in[1];
    const float* w2 = (const float*)d_in[2];
    const float* w3 = (const float*)d_in[3];
    const int* ia1 = (const int*)d_in[4];
    const int* ib1 = (const int*)d_in[5];
    const int* ia2 = (const int*)d_in[6];
    const int* ib2 = (const int*)d_in[7];
    const int* ia3 = (const int*)d_in[8];
    const int* ib3 = (const int*)d_in[9];
    float* out = (float*)d_out;

    precompute_kernel<<<(NNEUR + 255) / 256, 256>>>(w1, w2, w3, ia1, ib1, ia2, ib2, ia3, ib3);

    uint16_t *perm1, *inv1, *perm2, *inv2, *perm3;
    cudaGetSymbolAddress((void**)&perm1, d_perm1);
    cudaGetSymbolAddress((void**)&inv1,  d_inv1);
    cudaGetSymbolAddress((void**)&perm2, d_perm2);
    cudaGetSymbolAddress((void**)&inv2,  d_inv2);
    cudaGetSymbolAddress((void**)&perm3, d_perm3);

    // smem: off[CELLS][VW+8] + chbase[CELLS][4] + 3*CELLS + ufp[D]  (uint16)
    size_t smP1 = ((size_t)CELLS * (8192 / 32 + 8) + CELLS * 4 + 3 * CELLS + 8192) * sizeof(uint16_t);
    size_t smP3 = ((size_t)CELLS * (1024 / 32 + 8) + CELLS * 4 + 3 * CELLS + 1024) * sizeof(uint16_t);
    cudaFuncSetAttribute(build_perm_kernel<8192>, cudaFuncAttributeMaxDynamicSharedMemorySize, (int)smP1);
    cudaFuncSetAttribute(build_perm_kernel<1024>, cudaFuncAttributeMaxDynamicSharedMemorySize, (int)smP3);

    build_perm_kernel<8192><<<1, 1024, smP1>>>(0,        nullptr, perm1, inv1);
    build_perm_kernel<8192><<<1, 1024, smP1>>>(D1,       inv1,    perm2, inv2);
    build_perm_kernel<1024><<<KCLS, 1024, smP3>>>(D1 + D2, inv2,   perm3, nullptr);
    merge_meta_kernel<<<(NNEUR + 255) / 256, 256>>>();

    size_t smem = (size_t)(D0 + D1 + D2) * sizeof(uint2)
                + (size_t)(KCLS * NWARP * ROWS) * sizeof(float);
    cudaFuncSetAttribute(diff_logic_main, cudaFuncAttributeMaxDynamicSharedMemorySize, (int)smem);

    diff_logic_main<<<B_SZ / ROWS, NTHREADS, smem>>>(x, out);
}

// round 6
// speedup vs baseline: 1.3803x; 1.3803x over previous
#include <cuda_runtime.h>
#include <cuda_fp16.h>
#include <stdint.h>

#define B_SZ     4096
#define D0       1024
#define D1       8192
#define D2       8192
#define D3       10240
#define NNEUR    (D1 + D2 + D3)     // 26624
#define KCLS     10
#define GRP      (D3 / KCLS)        // 1024
#define TAU      30.0f
#define ROWS     2                  // batch rows per CTA (4096/2 = 2048 CTAs)
#define NTHREADS 1024
#define NWARP    (NTHREADS / 32)    // 32

// -------- precomputed per-neuron metadata (device globals, no allocs) --------
__device__ uint32_t g_idx[NNEUR];    // ia | (ib<<16)
__device__ uint2    g_coef[NNEUR];   // {half2(c0,c1), half2(c2,c3)}

__constant__ float OPC[16][4] = {
    {0.f, 0.f, 0.f, 0.f}, {0.f, 0.f, 0.f, 1.f}, {0.f, 1.f, 0.f, -1.f}, {0.f, 1.f, 0.f, 0.f},
    {0.f, 0.f, 1.f, -1.f}, {0.f, 0.f, 1.f, 0.f}, {0.f, 1.f, 1.f, -2.f}, {0.f, 1.f, 1.f, -1.f},
    {1.f, -1.f, -1.f, 1.f}, {1.f, -1.f, -1.f, 2.f}, {1.f, 0.f, -1.f, 0.f}, {1.f, 0.f, -1.f, 1.f},
    {1.f, -1.f, 0.f, 0.f}, {1.f, -1.f, 0.f, 1.f}, {1.f, 0.f, 0.f, -1.f}, {1.f, 0.f, 0.f, 0.f}};

__global__ void precompute_kernel(
    const float* __restrict__ w1, const float* __restrict__ w2, const float* __restrict__ w3,
    const int* __restrict__ ia1, const int* __restrict__ ib1,
    const int* __restrict__ ia2, const int* __restrict__ ib2,
    const int* __restrict__ ia3, const int* __restrict__ ib3)
{
    int j = blockIdx.x * blockDim.x + threadIdx.x;
    if (j >= NNEUR) return;
    const float* w; int ia, ib;
    if (j < D1)            { w = w1 + (size_t)j * 16;               ia = ia1[j];            ib = ib1[j]; }
    else if (j < D1 + D2)  { int k = j - D1;      w = w2 + (size_t)k * 16; ia = ia2[k]; ib = ib2[k]; }
    else                   { int k = j - D1 - D2; w = w3 + (size_t)k * 16; ia = ia3[k]; ib = ib3[k]; }

    float v[16]; float m = -3.4e38f;
#pragma unroll
    for (int i = 0; i < 16; i++) { v[i] = w[i]; m = fmaxf(m, v[i]); }
    float s = 0.f;
#pragma unroll
    for (int i = 0; i < 16; i++) { v[i] = expf(v[i] - m); s += v[i]; }
    float inv = 1.f / s;
    float c0 = 0.f, c1 = 0.f, c2 = 0.f, c3 = 0.f;
#pragma unroll
    for (int i = 0; i < 16; i++) {
        float p = v[i] * inv;
        c0 = fmaf(p, OPC[i][0], c0);
        c1 = fmaf(p, OPC[i][1], c1);
        c2 = fmaf(p, OPC[i][2], c2);
        c3 = fmaf(p, OPC[i][3], c3);
    }
    g_idx[j] = (uint32_t)ia | ((uint32_t)ib << 16);
    __half2 h01 = __floats2half2_rn(c0, c1);
    __half2 h23 = __floats2half2_rn(c2, c3);
    g_coef[j] = make_uint2(*reinterpret_cast<uint32_t*>(&h01),
                           *reinterpret_cast<uint32_t*>(&h23));
}

// -------- main kernel: whole network resident in shared memory --------------
// ROWS=2: one half2 (4B) smem slot per neuron. smem/CTA ~39.4KB -> 2 CTAs/SM,
// 64 warps/SM. Gathers are single LDS.32; stores conflict-free STS.32.

struct NeuronIn {
    uint32_t pk, u01, u23;
    uint32_t a, b;           // half2 each
};

__device__ __forceinline__ void fetch_neuron(const uint32_t* __restrict__ src,
                                             int mj, NeuronIn& n)
{
    n.pk  = __ldg(&g_idx[mj]);
    uint2 cc = __ldg(&g_coef[mj]);
    n.u01 = cc.x;
    n.u23 = cc.y;
    n.a = src[n.pk & 0xffffu];
    n.b = src[n.pk >> 16];
}

__device__ __forceinline__ uint32_t neuron_math(const NeuronIn& n)
{
    float2 c01 = __half22float2(*reinterpret_cast<const __half2*>(&n.u01));
    float2 c23 = __half22float2(*reinterpret_cast<const __half2*>(&n.u23));
    float2 a = __half22float2(*reinterpret_cast<const __half2*>(&n.a));
    float2 b = __half22float2(*reinterpret_cast<const __half2*>(&n.b));
    // c0 + c1*a + c2*b + c3*a*b = (c1 + c3*b)*a + (c0 + c2*b)
    float o0 = fmaf(fmaf(c23.y, b.x, c01.y), a.x, fmaf(c23.x, b.x, c01.x));
    float o1 = fmaf(fmaf(c23.y, b.y, c01.y), a.y, fmaf(c23.x, b.y, c01.x));
    __half2 h = __floats2half2_rn(o0, o1);
    return *reinterpret_cast<uint32_t*>(&h);
}

// D is a multiple of 2*NTHREADS for all layers, so the 2-deep pipeline
// needs no tail guards.
__device__ __forceinline__ void run_layer(const uint32_t* __restrict__ src,
                                          uint32_t* __restrict__ dst,
                                          int metaBase, int D, int tid)
{
    const int iters = D / NTHREADS;
    NeuronIn cur, nxt;
    int j = tid;
    fetch_neuron(src, metaBase + j, cur);
#pragma unroll 2
    for (int it = 0; it < iters - 1; it++) {
        fetch_neuron(src, metaBase + j + NTHREADS, nxt);
        dst[j] = neuron_math(cur);
        cur = nxt;
        j += NTHREADS;
    }
    dst[j] = neuron_math(cur);
}

__global__ void __launch_bounds__(NTHREADS, 2)
diff_logic_main(const float* __restrict__ x, float* __restrict__ out)
{
    extern __shared__ __align__(16) uint32_t smem_raw[];
    uint32_t* xs = smem_raw;                          // D0 slots (half2 each)
    uint32_t* h1 = xs + D0;                           // D1 slots
    uint32_t* h2 = h1 + D1;                           // D2 slots
    float* wacc = reinterpret_cast<float*>(h2 + D2);  // KCLS*NWARP*ROWS floats

    const int tid  = threadIdx.x;
    const int row0 = blockIdx.x * ROWS;               // exact: 4096 = 2048*2

    {   // load 2 batch rows of x: thread owns column tid (D0 == NTHREADS)
        int col = tid;
        float v0 = x[(size_t)(row0 + 0) * D0 + col];
        float v1 = x[(size_t)(row0 + 1) * D0 + col];
        __half2 p = __floats2half2_rn(v0, v1);
        xs[col] = *reinterpret_cast<uint32_t*>(&p);
    }
    __syncthreads();

    run_layer(xs, h1, 0, D1, tid);
    __syncthreads();
    run_layer(h1, h2, D1, D2, tid);
    __syncthreads();

    // Layer 3 fused with group-sum: never materialized.
    const int lane = tid & 31;
    const int warp = tid >> 5;

    for (int g = 0; g < KCLS; g++) {
        float acc0 = 0.f, acc1 = 0.f;
        {   // GRP == NTHREADS: one neuron per thread per group
            int mj = D1 + D2 + g * GRP + tid;
            NeuronIn n;
            fetch_neuron(h2, mj, n);
            float2 c01 = __half22float2(*reinterpret_cast<const __half2*>(&n.u01));
            float2 c23 = __half22float2(*reinterpret_cast<const __half2*>(&n.u23));
            float2 a = __half22float2(*reinterpret_cast<const __half2*>(&n.a));
            float2 b = __half22float2(*reinterpret_cast<const __half2*>(&n.b));
            acc0 = fmaf(fmaf(c23.y, b.x, c01.y), a.x, fmaf(c23.x, b.x, c01.x));
            acc1 = fmaf(fmaf(c23.y, b.y, c01.y), a.y, fmaf(c23.x, b.y, c01.x));
        }
        // Deterministic reduction: warp shuffle -> per-warp partials in smem.
#pragma unroll
        for (int off = 16; off > 0; off >>= 1) {
            acc0 += __shfl_down_sync(0xffffffffu, acc0, off);
            acc1 += __shfl_down_sync(0xffffffffu, acc1, off);
        }
        if (lane == 0) {
            wacc[(g * NWARP + warp) * ROWS + 0] = acc0;
            wacc[(g * NWARP + warp) * ROWS + 1] = acc1;
        }
    }
    __syncthreads();

    if (tid < KCLS * ROWS) {
        int g = tid / ROWS;
        int r = tid - g * ROWS;
        float s = 0.f;
#pragma unroll
        for (int w = 0; w < NWARP; w++)
            s += wacc[(g * NWARP + w) * ROWS + r];
        out[(size_t)(row0 + r) * KCLS + g] = s * (1.f / TAU);
    }
}

// -----------------------------------------------------------------------------

extern "C" void kernel_launch(void* const* d_in, const int* in_sizes, int n_in,
                              void* d_out, int out_size)
{
    (void)in_sizes; (void)n_in; (void)out_size;
    const float* x  = (const float*)d_in[0];
    const float* w1 = (const float*)d_in[1];
    const float* w2 = (const float*)d_in[2];
    const float* w3 = (const float*)d_in[3];
    const int* ia1 = (const int*)d_in[4];
    const int* ib1 = (const int*)d_in[5];
    const int* ia2 = (const int*)d_in[6];
    const int* ib2 = (const int*)d_in[7];
    const int* ia3 = (const int*)d_in[8];
    const int* ib3 = (const int*)d_in[9];
    float* out = (float*)d_out;

    precompute_kernel<<<(NNEUR + 255) / 256, 256>>>(w1, w2, w3, ia1, ib1, ia2, ib2, ia3, ib3);

    size_t smem = (size_t)(D0 + D1 + D2) * sizeof(uint32_t)
                + (size_t)(KCLS * NWARP * ROWS) * sizeof(float);   // 39,424 B
    cudaFuncSetAttribute(diff_logic_main, cudaFuncAttributeMaxDynamicSharedMemorySize, (int)smem);

    diff_logic_main<<<B_SZ / ROWS, NTHREADS, smem>>>(x, out);
}

// round 7
// speedup vs baseline: 1.5104x; 1.0942x over previous
#include <cuda_runtime.h>
#include <cuda_fp16.h>
#include <stdint.h>

#define B_SZ     4096
#define D0       1024
#define D1       8192
#define D2       8192
#define D3       10240
#define NNEUR    (D1 + D2 + D3)     // 26624
#define KCLS     10
#define GRP      (D3 / KCLS)        // 1024
#define TAU      30.0f
#define ROWS     4                  // batch rows per CTA
#define NTHREADS 1024
#define NWARP    (NTHREADS / 32)    // 32
#define CELLS    256                // 16 a-bank-pairs x 16 b-bank-pairs
#define CHUNK    1024               // deal window pool (per builder CTA)
#define NCHUNK   (NNEUR / CHUNK)    // 26
#define CAP      (CHUNK / CELLS)    // 4

// -------- staging (original order) --------
__device__ uint32_t s_idx[NNEUR];
__device__ uint32_t s_c01[NNEUR];
__device__ uint32_t s_c23[NNEUR];
// -------- dealt processing order + final metadata --------
__device__ uint16_t d_order[NNEUR];  // slot -> original global neuron id
__device__ uint4    g_meta[NNEUR];   // {ia|ib<<16, dst, half2(c0,c1), half2(c2,c3)}

__constant__ float OPC[16][4] = {
    {0.f, 0.f, 0.f, 0.f}, {0.f, 0.f, 0.f, 1.f}, {0.f, 1.f, 0.f, -1.f}, {0.f, 1.f, 0.f, 0.f},
    {0.f, 0.f, 1.f, -1.f}, {0.f, 0.f, 1.f, 0.f}, {0.f, 1.f, 1.f, -2.f}, {0.f, 1.f, 1.f, -1.f},
    {1.f, -1.f, -1.f, 1.f}, {1.f, -1.f, -1.f, 2.f}, {1.f, 0.f, -1.f, 0.f}, {1.f, 0.f, -1.f, 1.f},
    {1.f, -1.f, 0.f, 0.f}, {1.f, -1.f, 0.f, 1.f}, {1.f, 0.f, 0.f, -1.f}, {1.f, 0.f, 0.f, 0.f}};

__global__ void precompute_kernel(
    const float* __restrict__ w1, const float* __restrict__ w2, const float* __restrict__ w3,
    const int* __restrict__ ia1, const int* __restrict__ ib1,
    const int* __restrict__ ia2, const int* __restrict__ ib2,
    const int* __restrict__ ia3, const int* __restrict__ ib3)
{
    int j = blockIdx.x * blockDim.x + threadIdx.x;
    if (j >= NNEUR) return;
    const float* w; int ia, ib;
    if (j < D1)            { w = w1 + (size_t)j * 16;               ia = ia1[j];            ib = ib1[j]; }
    else if (j < D1 + D2)  { int k = j - D1;      w = w2 + (size_t)k * 16; ia = ia2[k]; ib = ib2[k]; }
    else                   { int k = j - D1 - D2; w = w3 + (size_t)k * 16; ia = ia3[k]; ib = ib3[k]; }

    float v[16]; float m = -3.4e38f;
#pragma unroll
    for (int i = 0; i < 16; i++) { v[i] = w[i]; m = fmaxf(m, v[i]); }
    float s = 0.f;
#pragma unroll
    for (int i = 0; i < 16; i++) { v[i] = expf(v[i] - m); s += v[i]; }
    float inv = 1.f / s;
    float c0 = 0.f, c1 = 0.f, c2 = 0.f, c3 = 0.f;
#pragma unroll
    for (int i = 0; i < 16; i++) {
        float p = v[i] * inv;
        c0 = fmaf(p, OPC[i][0], c0);
        c1 = fmaf(p, OPC[i][1], c1);
        c2 = fmaf(p, OPC[i][2], c2);
        c3 = fmaf(p, OPC[i][3], c3);
    }
    s_idx[j] = (uint32_t)ia | ((uint32_t)ib << 16);
    __half2 h01 = __floats2half2_rn(c0, c1);
    __half2 h23 = __floats2half2_rn(c2, c3);
    s_c01[j] = *reinterpret_cast<uint32_t*>(&h01);
    s_c23[j] = *reinterpret_cast<uint32_t*>(&h23);
}

// ---- dealt-order builder: one CTA per 1024-neuron chunk, all independent ----
// Assigns each neuron a processing slot so that each 32-slot warp window has
// 16 distinct a-banks and b-banks per half-warp (conflict-free LDS.64 gathers).
// Deterministic: __match_any ranks + warp-shuffle scans. No atomics.
__global__ void __launch_bounds__(1024, 1)
build_order_kernel()
{
    constexpr int SCNSTR = 40;                    // 32 warps + pad
    __shared__ uint16_t off[CELLS * SCNSTR];      // per (cell,warp) counts -> exclusive
    __shared__ uint16_t chbase[CELLS * 4];        // per (cell,chunk-of-8-warps) bases
    __shared__ uint16_t csize[CELLS], exoff[CELLS], ufoff[CELLS];
    __shared__ uint16_t ufp[CHUNK];
    __shared__ int wte[8], wtu[8];

    const int tid  = threadIdx.x;
    const int lane = tid & 31;
    const int w    = tid >> 5;
    const uint32_t ltm = (1u << lane) - 1u;
    const int base = blockIdx.x * CHUNK;          // chunks align with layers/groups

    for (int i = tid; i < CELLS * SCNSTR / 2; i += 1024)
        reinterpret_cast<uint32_t*>(off)[i] = 0;
    __syncthreads();

    // count
    uint32_t pk = s_idx[base + tid];
    int cell = (int)((pk & 15u) * 16u + ((pk >> 16) & 15u));
    uint32_t mask = __match_any_sync(0xffffffffu, cell);
    int lr = __popc(mask & ltm);
    if ((mask & ltm) == 0)
        off[cell * SCNSTR + w] = (uint16_t)__popc(mask);
    __syncthreads();

    // phase 1: per-(cell, 8-warp chunk) exclusive scan
    {
        int c  = tid >> 2;
        int ch = tid & 3;
        int bo = c * SCNSTR + ch * 8;
        uint16_t run = 0;
#pragma unroll
        for (int i = 0; i < 8; i++) {
            uint16_t t = off[bo + i];
            off[bo + i] = run;
            run = (uint16_t)(run + t);
        }
        chbase[c * 4 + ch] = run;                 // chunk totals (temp)
    }
    __syncthreads();

    // phase 2: per-cell combine -> sizes, excess/unfilled
    if (tid < CELLS) {
        int c = tid; uint16_t b = 0;
#pragma unroll
        for (int ch = 0; ch < 4; ch++) {
            uint16_t t = chbase[c * 4 + ch];
            chbase[c * 4 + ch] = b;
            b = (uint16_t)(b + t);
        }
        csize[c] = b;
        exoff[c] = (b > CAP) ? (uint16_t)(b - CAP) : 0;
        ufoff[c] = (b < CAP) ? (uint16_t)(CAP - b) : 0;
    }
    __syncthreads();

    // inclusive scans over 256 cells via warp shuffles (warps 0..7)
    int e = 0, u = 0;
    if (tid < CELLS) { e = exoff[tid]; u = ufoff[tid]; }
    if (tid < CELLS) {
#pragma unroll
        for (int o = 1; o < 32; o <<= 1) {
            int pe = __shfl_up_sync(0xffffffffu, e, o);
            int pu = __shfl_up_sync(0xffffffffu, u, o);
            if (lane >= o) { e += pe; u += pu; }
        }
        if (lane == 31) { wte[w] = e; wtu[w] = u; }
    }
    __syncthreads();
    if (tid == 0) {
        int be = 0, bu = 0;
#pragma unroll
        for (int i = 0; i < 8; i++) {
            int te = wte[i], tu = wtu[i];
            wte[i] = be; wtu[i] = bu;
            be += te; bu += tu;
        }
    }
    __syncthreads();
    if (tid < CELLS) {
        exoff[tid] = (uint16_t)(e + wte[w]);
        ufoff[tid] = (uint16_t)(u + wtu[w]);
    }
    __syncthreads();

    // emit unfilled dealt positions, grouped by cell
    if (tid < CELLS) {
        int c = tid, t = c >> 4, s = c & 15;
        int sz  = csize[c];
        int ufc = (sz < CAP) ? CAP - sz : 0;
        int ub  = ufoff[c] - ufc;                 // exclusive offset
        for (int m = sz; m < CAP; m++)
            ufp[ub + (m - sz)] = (uint16_t)((((s - t) & 15) + 16 * m) * 16 + t);
    }
    __syncthreads();

    // assign slots
    {
        int grank = off[cell * SCNSTR + w] + chbase[cell * 4 + (w >> 3)] + lr;
        int t = cell >> 4, s = cell & 15;
        int p;
        if (grank < CAP) {
            p = (((s - t) & 15) + 16 * grank) * 16 + t;
        } else {
            int exc = csize[cell] - CAP;          // > 0 here
            int exb = exoff[cell] - exc;
            p = ufp[exb + (grank - CAP)];
        }
        d_order[base + p] = (uint16_t)(base + tid);
    }
}

// ---- merge: gather metadata into dealt order, carry dst position ----------
__global__ void merge_meta_kernel()
{
    int s = blockIdx.x * blockDim.x + threadIdx.x;
    if (s >= NNEUR) return;
    int o = d_order[s];
    int lb = (o < D1) ? 0 : ((o < D1 + D2) ? D1 : D1 + D2);
    g_meta[s] = make_uint4(s_idx[o], (uint32_t)(o - lb), s_c01[o], s_c23[o]);
}

// -------- main kernel: whole network resident in shared memory --------------
// ROWS=4: uint2 (8B) slot per neuron; layouts of xs/h1/h2 are ORIGINAL order
// (only processing order is dealt), so no index remapping anywhere.

struct NeuronIn {
    uint32_t pk, dst, u01, u23;
    uint2 a, b;
};

__device__ __forceinline__ void fetch_neuron(const uint2* __restrict__ src,
                                             int mj, NeuronIn& n)
{
    uint4 m = __ldg(&g_meta[mj]);
    n.pk = m.x; n.dst = m.y; n.u01 = m.z; n.u23 = m.w;
    n.a = src[m.x & 0xffffu];
    n.b = src[m.x >> 16];
}

__device__ __forceinline__ uint2 neuron_math(const NeuronIn& n)
{
    float2 c01 = __half22float2(*reinterpret_cast<const __half2*>(&n.u01));
    float2 c23 = __half22float2(*reinterpret_cast<const __half2*>(&n.u23));
    uint2 o;
#pragma unroll
    for (int r = 0; r < 2; r++) {
        uint32_t ua = (r == 0) ? n.a.x : n.a.y;
        uint32_t ub = (r == 0) ? n.b.x : n.b.y;
        float2 a = __half22float2(*reinterpret_cast<const __half2*>(&ua));
        float2 b = __half22float2(*reinterpret_cast<const __half2*>(&ub));
        float o0 = fmaf(fmaf(c23.y, b.x, c01.y), a.x, fmaf(c23.x, b.x, c01.x));
        float o1 = fmaf(fmaf(c23.y, b.y, c01.y), a.y, fmaf(c23.x, b.y, c01.x));
        __half2 h = __floats2half2_rn(o0, o1);
        uint32_t uh = *reinterpret_cast<uint32_t*>(&h);
        if (r == 0) o.x = uh; else o.y = uh;
    }
    return o;
}

__device__ __forceinline__ void run_layer(const uint2* __restrict__ src,
                                          uint2* __restrict__ dst,
                                          int metaBase, int D, int tid)
{
    const int iters = D / NTHREADS;
    NeuronIn cur, nxt;
    fetch_neuron(src, metaBase + tid, cur);
#pragma unroll 2
    for (int it = 0; it < iters - 1; it++) {
        fetch_neuron(src, metaBase + (it + 1) * NTHREADS + tid, nxt);
        dst[cur.dst] = neuron_math(cur);
        cur = nxt;
    }
    dst[cur.dst] = neuron_math(cur);
}

__global__ void __launch_bounds__(NTHREADS, 1)
diff_logic_main(const float* __restrict__ x, float* __restrict__ out)
{
    extern __shared__ __align__(16) uint32_t smem_raw[];
    uint2* xs = reinterpret_cast<uint2*>(smem_raw);
    uint2* h1 = xs + D0;
    uint2* h2 = h1 + D1;
    float* wacc = reinterpret_cast<float*>(h2 + D2);

    const int tid  = threadIdx.x;
    const int row0 = blockIdx.x * ROWS;

    {
        int col = tid;                            // D0 == NTHREADS
        float v0 = x[(size_t)(row0 + 0) * D0 + col];
        float v1 = x[(size_t)(row0 + 1) * D0 + col];
        float v2 = x[(size_t)(row0 + 2) * D0 + col];
        float v3 = x[(size_t)(row0 + 3) * D0 + col];
        __half2 p0 = __floats2half2_rn(v0, v1);
        __half2 p1 = __floats2half2_rn(v2, v3);
        uint2 slot;
        slot.x = *reinterpret_cast<uint32_t*>(&p0);
        slot.y = *reinterpret_cast<uint32_t*>(&p1);
        xs[col] = slot;
    }
    __syncthreads();

    run_layer(xs, h1, 0, D1, tid);
    __syncthreads();
    run_layer(h1, h2, D1, D2, tid);
    __syncthreads();

    // Layer 3 fused with group-sum (dealt order within each group; group sums
    // unchanged up to fp add order).
    const int lane = tid & 31;
    const int warp = tid >> 5;

    for (int g = 0; g < KCLS; g++) {
        float acc[ROWS];
#pragma unroll
        for (int r = 0; r < ROWS; r++) acc[r] = 0.f;
        {
            int mj = D1 + D2 + g * GRP + tid;     // GRP == NTHREADS
            NeuronIn n;
            fetch_neuron(h2, mj, n);
            float2 c01 = __half22float2(*reinterpret_cast<const __half2*>(&n.u01));
            float2 c23 = __half22float2(*reinterpret_cast<const __half2*>(&n.u23));
#pragma unroll
            for (int r = 0; r < 2; r++) {
                uint32_t ua = (r == 0) ? n.a.x : n.a.y;
                uint32_t ub = (r == 0) ? n.b.x : n.b.y;
                float2 a = __half22float2(*reinterpret_cast<const __half2*>(&ua));
                float2 b = __half22float2(*reinterpret_cast<const __half2*>(&ub));
                acc[2 * r + 0] = fmaf(fmaf(c23.y, b.x, c01.y), a.x, fmaf(c23.x, b.x, c01.x));
                acc[2 * r + 1] = fmaf(fmaf(c23.y, b.y, c01.y), a.y, fmaf(c23.x, b.y, c01.x));
            }
        }
#pragma unroll
        for (int r = 0; r < ROWS; r++) {
#pragma unroll
            for (int off = 16; off > 0; off >>= 1)
                acc[r] += __shfl_down_sync(0xffffffffu, acc[r], off);
        }
        if (lane == 0) {
#pragma unroll
            for (int r = 0; r < ROWS; r++)
                wacc[(g * NWARP + warp) * ROWS + r] = acc[r];
        }
    }
    __syncthreads();

    if (tid < KCLS * ROWS) {
        int g = tid / ROWS;
        int r = tid - g * ROWS;
        float s = 0.f;
#pragma unroll
        for (int w = 0; w < NWARP; w++)
            s += wacc[(g * NWARP + w) * ROWS + r];
        out[(size_t)(row0 + r) * KCLS + g] = s * (1.f / TAU);
    }
}

// -----------------------------------------------------------------------------

extern "C" void kernel_launch(void* const* d_in, const int* in_sizes, int n_in,
                              void* d_out, int out_size)
{
    (void)in_sizes; (void)n_in; (void)out_size;
    const float* x  = (const float*)d_in[0];
    const float* w1 = (const float*)d_in[1];
    const float* w2 = (const float*)d_in[2];
    const float* w3 = (const float*)d_in[3];
    const int* ia1 = (const int*)d_in[4];
    const int* ib1 = (const int*)d_in[5];
    const int* ia2 = (const int*)d_in[6];
    const int* ib2 = (const int*)d_in[7];
    const int* ia3 = (const int*)d_in[8];
    const int* ib3 = (const int*)d_in[9];
    float* out = (float*)d_out;

    precompute_kernel<<<(NNEUR + 255) / 256, 256>>>(w1, w2, w3, ia1, ib1, ia2, ib2, ia3, ib3);
    build_order_kernel<<<NCHUNK, 1024>>>();                // 26 independent CTAs
    merge_meta_kernel<<<(NNEUR + 255) / 256, 256>>>();

    size_t smem = (size_t)(D0 + D1 + D2) * sizeof(uint2)
                + (size_t)(KCLS * NWARP * ROWS) * sizeof(float);   // 144,384 B
    cudaFuncSetAttribute(diff_logic_main, cudaFuncAttributeMaxDynamicSharedMemorySize, (int)smem);

    diff_logic_main<<<B_SZ / ROWS, NTHREADS, smem>>>(x, out);
}